// round 8
// baseline (speedup 1.0000x reference)
#include <cuda_runtime.h>
#include <cuda_fp16.h>
#include <cstdint>

#define NVARS 256
#define BM 32
#define SROW 264  // halves per padded smem row (528B): conflict-free ldmatrix/LDS.128

// W[n][k] = V[n][k] for k>n else 0  (V = M^{-1}; identity added in fp32 epilogue)
__device__ __half g_W[NVARS * NVARS];

__device__ __forceinline__ uint32_t smem_to_u32(const void* smem_ptr) {
    uint32_t addr;
    asm("{ .reg .u64 tmp; cvta.to.shared.u64 tmp, %1; cvt.u32.u64 %0, tmp; }"
        : "=r"(addr) : "l"(smem_ptr));
    return addr;
}

__device__ __forceinline__ void ldmx4(uint32_t* d, uint32_t addr) {
    asm volatile("ldmatrix.sync.aligned.m8n8.x4.shared.b16 {%0,%1,%2,%3}, [%4];"
                 : "=r"(d[0]), "=r"(d[1]), "=r"(d[2]), "=r"(d[3])
                 : "r"(addr));
}

__device__ __forceinline__ void mma16816(float* c, const uint32_t* a,
                                         uint32_t b0, uint32_t b1) {
    asm volatile(
        "mma.sync.aligned.m16n8k16.row.col.f32.f16.f16.f32 "
        "{%0,%1,%2,%3}, {%4,%5,%6,%7}, {%8,%9}, {%0,%1,%2,%3};"
        : "+f"(c[0]), "+f"(c[1]), "+f"(c[2]), "+f"(c[3])
        : "r"(a[0]), "r"(a[1]), "r"(a[2]), "r"(a[3]), "r"(b0), "r"(b1));
}

__device__ __forceinline__ uint4 cvt8_f32_to_h8(const float4 f0, const float4 f1) {
    __half2 h0 = __floats2half2_rn(f0.x, f0.y);
    __half2 h1 = __floats2half2_rn(f0.z, f0.w);
    __half2 h2 = __floats2half2_rn(f1.x, f1.y);
    __half2 h3 = __floats2half2_rn(f1.z, f1.w);
    uint4 u;
    u.x = *reinterpret_cast<uint32_t*>(&h0);
    u.y = *reinterpret_cast<uint32_t*>(&h1);
    u.z = *reinterpret_cast<uint32_t*>(&h2);
    u.w = *reinterpret_cast<uint32_t*>(&h3);
    return u;
}

// ---------------------------------------------------------------------------
// Kernel 1: triangular inverse (fused). 32 CTAs x 256 thr; warp per row r.
// ---------------------------------------------------------------------------
static constexpr int IM_A_HALVES = NVARS * SROW;  // 67584
static constexpr int BINV_STRIDE = 33;            // padded: conflict-free rows
static constexpr int IM_BINV_FLOATS = 8 * 32 * BINV_STRIDE;  // 8448
static constexpr int IM_SMEM =
    IM_A_HALVES * 2 + IM_BINV_FLOATS * 4 + 8 * NVARS * 4;  // 177152

__global__ __launch_bounds__(256) void invmain_kernel(const float* __restrict__ A) {
    extern __shared__ __align__(16) char sm_raw[];
    __half* A_s = reinterpret_cast<__half*>(sm_raw);
    float* Binv_s = reinterpret_cast<float*>(sm_raw + IM_A_HALVES * 2);
    float(*Vsm_all)[NVARS] = reinterpret_cast<float(*)[NVARS]>(
        sm_raw + IM_A_HALVES * 2 + IM_BINV_FLOATS * 4);

    const int tid = threadIdx.x;
    const int warp = tid >> 5;
    const int lane = tid & 31;
    const int r = blockIdx.x * 8 + warp;
    const int d0 = r >> 5;
    const int j0c = (blockIdx.x >> 2) * 32;  // first A row this CTA needs
    float* Vsm = Vsm_all[warp];

    for (int idx = tid; idx < (NVARS - j0c) * 64; idx += 256) {
        const int row = j0c + (idx >> 6);
        const int cs = (idx & 63) * 4;
        const float4 f = *reinterpret_cast<const float4*>(A + (size_t)row * NVARS + cs);
        __half2 h0 = __floats2half2_rn(f.x, f.y);
        __half2 h1 = __floats2half2_rn(f.z, f.w);
        uint2 u;
        u.x = *reinterpret_cast<uint32_t*>(&h0);
        u.y = *reinterpret_cast<uint32_t*>(&h1);
        *reinterpret_cast<uint2*>(A_s + row * SROW + cs) = u;
    }
    __syncthreads();

    if (warp >= d0) {
        const int c0 = warp * 32;
        const __half* Ab = A_s + (size_t)c0 * SROW + c0;
        float B[32];
#pragma unroll
        for (int t = 0; t < 32; ++t) B[t] = 0.0f;
        B[lane] = 1.0f;
#pragma unroll
        for (int t = 1; t < 32; ++t) {
            float s = 0.0f;
#pragma unroll
            for (int x = 0; x < t; ++x)
                s = fmaf(B[x], __half2float(Ab[t * SROW + x]), s);
            if (t > lane) B[t] = s;
        }
        float* Bo = Binv_s + warp * 32 * BINV_STRIDE + lane * BINV_STRIDE;
#pragma unroll
        for (int t = 0; t < 32; ++t) Bo[t] = B[t];
    }
    __syncthreads();

    for (int d = 0; d < d0; ++d)
        g_W[r * NVARS + d * 32 + lane] = __float2half(0.0f);

    const int j0 = d0 * 32;
    for (int d = d0; d < 8; ++d) {
        const int c0 = d * 32;
        float v;
        if (d == d0) {
            v = Binv_s[d0 * 32 * BINV_STRIDE + (r & 31) * BINV_STRIDE + lane];
        } else {
            const __half* Arow = A_s + (c0 + lane) * SROW;
            float s0 = 0.f, s1 = 0.f, s2 = 0.f, s3 = 0.f;
            for (int j = j0; j < c0; j += 8) {
                const uint4 u = *reinterpret_cast<const uint4*>(Arow + j);
                const __half2* h = reinterpret_cast<const __half2*>(&u);
                const float2 f0 = __half22float2(h[0]);
                const float2 f1 = __half22float2(h[1]);
                const float2 f2 = __half22float2(h[2]);
                const float2 f3 = __half22float2(h[3]);
                s0 = fmaf(Vsm[j + 0], f0.x, s0);
                s1 = fmaf(Vsm[j + 1], f0.y, s1);
                s2 = fmaf(Vsm[j + 2], f1.x, s2);
                s3 = fmaf(Vsm[j + 3], f1.y, s3);
                s0 = fmaf(Vsm[j + 4], f2.x, s0);
                s1 = fmaf(Vsm[j + 5], f2.y, s1);
                s2 = fmaf(Vsm[j + 6], f3.x, s2);
                s3 = fmaf(Vsm[j + 7], f3.y, s3);
            }
            const float S = (s0 + s1) + (s2 + s3);
            v = 0.0f;
            const float* Bi = Binv_s + d * 32 * BINV_STRIDE + lane;
#pragma unroll
            for (int u = 0; u < 32; ++u) {
                const float su = __shfl_sync(0xffffffffu, S, u);
                v = fmaf(su, Bi[u * BINV_STRIDE], v);
            }
        }
        Vsm[c0 + lane] = v;
        __syncwarp();
        g_W[r * NVARS + c0 + lane] = __float2half((c0 + lane > r) ? v : 0.0f);
    }
}

// ---------------------------------------------------------------------------
// Kernel 2: persistent GEMM, N-split pairs + double buffer + reg prefetch.
// CTA: BM=32 x NH=128 x K=256. W half (33.8KB) + 2 Z bufs (33.8KB) = 67.6KB.
// __launch_bounds__(256,2) -> 2 CTAs/SM, 16 warps/SM.
// 8 warps: 2(M,16) x 4(N,32); warp tile 16x32.
// ---------------------------------------------------------------------------
static constexpr int NH = 128;
static constexpr int SMEM_W_HALVES = NH * SROW;  // 33792
static constexpr int SMEM_Z_HALVES = BM * SROW;  // 8448 per buf
static constexpr int SMEM_BYTES = (SMEM_W_HALVES + 2 * SMEM_Z_HALVES) * 2;  // 101376

__global__ __launch_bounds__(256, 2) void gemm_kernel(const float* __restrict__ Z,
                                                      float* __restrict__ out,
                                                      int batch, int ntiles) {
    extern __shared__ __align__(16) __half smem[];
    __half* Ws = smem;
    __half* Zbuf0 = smem + SMEM_W_HALVES;
    __half* Zbuf1 = Zbuf0 + SMEM_Z_HALVES;

    const int tid = threadIdx.x;
    const int lane = tid & 31;
    const int wid = tid >> 5;
    const int wm = wid & 1;   // M half (16 rows)
    const int wn = wid >> 1;  // N quarter of the half (32 cols)
    const int nbase = (blockIdx.x & 1) * NH;
    const int tstride = gridDim.x >> 1;

    // --- load W half into smem once ---
    for (int idx = tid; idx < NH * 32; idx += 256) {
        const int row = idx >> 5;
        const int seg = idx & 31;
        *reinterpret_cast<uint4*>(Ws + row * SROW + seg * 8) =
            *reinterpret_cast<const uint4*>(g_W + (size_t)(nbase + row) * NVARS + seg * 8);
    }

    // --- fragment addresses ---
    const uint32_t wbase = smem_to_u32(Ws);
    uint32_t baddr[2];
#pragma unroll
    for (int bj = 0; bj < 2; ++bj) {
        const int row = wn * 32 + bj * 16 + (lane & 7) + (((lane >> 4) & 1) * 8);
        const int cb = (lane & 8) ? 16 : 0;
        baddr[bj] = wbase + (uint32_t)row * (SROW * 2) + cb;
    }
    const int arow = wm * 16 + (lane & 15);
    const uint32_t acb = ((lane >> 4) & 1) * 16;

    // --- prefetch first tile (fp16-converted in regs) ---
    uint4 pf[4];
    int tile = blockIdx.x >> 1;
#pragma unroll
    for (int i = 0; i < 4; ++i) {
        const int idx = tid + i * 256;
        const int row = idx >> 5, seg = idx & 31;
        const int gr = tile * BM + row;
        if (tile < ntiles && gr < batch) {
            const float4* p =
                reinterpret_cast<const float4*>(Z + (size_t)gr * NVARS + seg * 8);
            pf[i] = cvt8_f32_to_h8(p[0], p[1]);
        } else {
            pf[i] = make_uint4(0, 0, 0, 0);
        }
    }

    int parity = 0;
    const int rrow = lane >> 2;
    const int rcol = (lane & 3) * 2;

    for (; tile < ntiles; tile += tstride) {
        __half* Zs = parity ? Zbuf1 : Zbuf0;

        // store prefetched tile
#pragma unroll
        for (int i = 0; i < 4; ++i) {
            const int idx = tid + i * 256;
            const int row = idx >> 5, seg = idx & 31;
            *reinterpret_cast<uint4*>(Zs + row * SROW + seg * 8) = pf[i];
        }

        // prefetch next tile (latency hidden under MMA)
        const int nt = tile + tstride;
        if (nt < ntiles) {
#pragma unroll
            for (int i = 0; i < 4; ++i) {
                const int idx = tid + i * 256;
                const int row = idx >> 5, seg = idx & 31;
                const int gr = nt * BM + row;
                if (gr < batch) {
                    const float4* p =
                        reinterpret_cast<const float4*>(Z + (size_t)gr * NVARS + seg * 8);
                    pf[i] = cvt8_f32_to_h8(p[0], p[1]);
                } else {
                    pf[i] = make_uint4(0, 0, 0, 0);
                }
            }
        }

        __syncthreads();  // staging visible; other buffer free

        const uint32_t zbase = smem_to_u32(Zs);
        const uint32_t aaddr = zbase + (uint32_t)arow * (SROW * 2) + acb;

        float acc[4][4];
#pragma unroll
        for (int nj = 0; nj < 4; ++nj)
#pragma unroll
            for (int e = 0; e < 4; ++e) acc[nj][e] = 0.0f;

#pragma unroll
        for (int k = 0; k < 16; ++k) {
            uint32_t a[4], b[2][4];
            ldmx4(a, aaddr + k * 32);
#pragma unroll
            for (int bj = 0; bj < 2; ++bj) ldmx4(b[bj], baddr[bj] + k * 32);
#pragma unroll
            for (int nj = 0; nj < 4; ++nj) {
                const int bj = nj >> 1;
                const int hi = (nj & 1) * 2;
                mma16816(acc[nj], a, b[bj][hi + 0], b[bj][hi + 1]);
            }
        }

        // --- epilogue: out = Z(fp32, L2-hot) + acc ---
        const int r0 = tile * BM + wm * 16 + rrow;
        const int r1 = r0 + 8;
#pragma unroll
        for (int nj = 0; nj < 4; ++nj) {
            const int c = nbase + wn * 32 + nj * 8 + rcol;
            if (r0 < batch) {
                const float2 z0 =
                    *reinterpret_cast<const float2*>(Z + (size_t)r0 * NVARS + c);
                float2 o0;
                o0.x = z0.x + acc[nj][0];
                o0.y = z0.y + acc[nj][1];
                *reinterpret_cast<float2*>(out + (size_t)r0 * NVARS + c) = o0;
            }
            if (r1 < batch) {
                const float2 z1 =
                    *reinterpret_cast<const float2*>(Z + (size_t)r1 * NVARS + c);
                float2 o1;
                o1.x = z1.x + acc[nj][2];
                o1.y = z1.y + acc[nj][3];
                *reinterpret_cast<float2*>(out + (size_t)r1 * NVARS + c) = o1;
            }
        }

        parity ^= 1;
    }
}

// ---------------------------------------------------------------------------
extern "C" void kernel_launch(void* const* d_in, const int* in_sizes, int n_in,
                              void* d_out, int out_size) {
    const float* Z = (const float*)d_in[0];
    const float* A = (const float*)d_in[1];
    float* out = (float*)d_out;
    const int batch = in_sizes[0] / NVARS;
    const int ntiles = (batch + BM - 1) / BM;

    cudaFuncSetAttribute(gemm_kernel, cudaFuncAttributeMaxDynamicSharedMemorySize,
                         SMEM_BYTES);
    cudaFuncSetAttribute(invmain_kernel, cudaFuncAttributeMaxDynamicSharedMemorySize,
                         IM_SMEM);

    invmain_kernel<<<32, 256, IM_SMEM>>>(A);

    int grid = 2 * 152;
    if (2 * ntiles < grid) grid = 2 * ntiles;
    gemm_kernel<<<grid, 256, SMEM_BYTES>>>(Z, out, batch, ntiles);
}

// round 12
// speedup vs baseline: 1.2326x; 1.2326x over previous
#include <cuda_runtime.h>
#include <cuda_fp16.h>
#include <cstdint>

#define NVARS 256
#define BM 32
#define SROW 264  // halves per padded smem row (528B): conflict-free ldmatrix/LDS.128

// W[n][k] = V[n][k] for k>n else 0  (V = M^{-1}; identity added in fp32 epilogue)
__device__ __half g_W[NVARS * NVARS];

__device__ __forceinline__ uint32_t smem_to_u32(const void* smem_ptr) {
    uint32_t addr;
    asm("{ .reg .u64 tmp; cvta.to.shared.u64 tmp, %1; cvt.u32.u64 %0, tmp; }"
        : "=r"(addr) : "l"(smem_ptr));
    return addr;
}

__device__ __forceinline__ void ldmx4(uint32_t* d, uint32_t addr) {
    asm volatile("ldmatrix.sync.aligned.m8n8.x4.shared.b16 {%0,%1,%2,%3}, [%4];"
                 : "=r"(d[0]), "=r"(d[1]), "=r"(d[2]), "=r"(d[3])
                 : "r"(addr));
}

__device__ __forceinline__ void mma16816(float* c, const uint32_t* a,
                                         uint32_t b0, uint32_t b1) {
    asm volatile(
        "mma.sync.aligned.m16n8k16.row.col.f32.f16.f16.f32 "
        "{%0,%1,%2,%3}, {%4,%5,%6,%7}, {%8,%9}, {%0,%1,%2,%3};"
        : "+f"(c[0]), "+f"(c[1]), "+f"(c[2]), "+f"(c[3])
        : "r"(a[0]), "r"(a[1]), "r"(a[2]), "r"(a[3]), "r"(b0), "r"(b1));
}

__device__ __forceinline__ uint4 cvt8_f32_to_h8(const float4 f0, const float4 f1) {
    __half2 h0 = __floats2half2_rn(f0.x, f0.y);
    __half2 h1 = __floats2half2_rn(f0.z, f0.w);
    __half2 h2 = __floats2half2_rn(f1.x, f1.y);
    __half2 h3 = __floats2half2_rn(f1.z, f1.w);
    uint4 u;
    u.x = *reinterpret_cast<uint32_t*>(&h0);
    u.y = *reinterpret_cast<uint32_t*>(&h1);
    u.z = *reinterpret_cast<uint32_t*>(&h2);
    u.w = *reinterpret_cast<uint32_t*>(&h3);
    return u;
}

// ---------------------------------------------------------------------------
// Kernel 1: triangular inverse (fused). 32 CTAs x 256 thr; warp per row r.
// ---------------------------------------------------------------------------
static constexpr int IM_A_HALVES = NVARS * SROW;  // 67584
static constexpr int BINV_STRIDE = 33;            // padded: conflict-free rows
static constexpr int IM_BINV_FLOATS = 8 * 32 * BINV_STRIDE;  // 8448
static constexpr int IM_SMEM =
    IM_A_HALVES * 2 + IM_BINV_FLOATS * 4 + 8 * NVARS * 4;  // 177152

__global__ __launch_bounds__(256) void invmain_kernel(const float* __restrict__ A) {
    extern __shared__ __align__(16) char sm_raw[];
    __half* A_s = reinterpret_cast<__half*>(sm_raw);
    float* Binv_s = reinterpret_cast<float*>(sm_raw + IM_A_HALVES * 2);
    float(*Vsm_all)[NVARS] = reinterpret_cast<float(*)[NVARS]>(
        sm_raw + IM_A_HALVES * 2 + IM_BINV_FLOATS * 4);

    const int tid = threadIdx.x;
    const int warp = tid >> 5;
    const int lane = tid & 31;
    const int r = blockIdx.x * 8 + warp;
    const int d0 = r >> 5;
    const int j0c = (blockIdx.x >> 2) * 32;  // first A row this CTA needs
    float* Vsm = Vsm_all[warp];

    for (int idx = tid; idx < (NVARS - j0c) * 64; idx += 256) {
        const int row = j0c + (idx >> 6);
        const int cs = (idx & 63) * 4;
        const float4 f = *reinterpret_cast<const float4*>(A + (size_t)row * NVARS + cs);
        __half2 h0 = __floats2half2_rn(f.x, f.y);
        __half2 h1 = __floats2half2_rn(f.z, f.w);
        uint2 u;
        u.x = *reinterpret_cast<uint32_t*>(&h0);
        u.y = *reinterpret_cast<uint32_t*>(&h1);
        *reinterpret_cast<uint2*>(A_s + row * SROW + cs) = u;
    }
    __syncthreads();

    if (warp >= d0) {
        const int c0 = warp * 32;
        const __half* Ab = A_s + (size_t)c0 * SROW + c0;
        float B[32];
#pragma unroll
        for (int t = 0; t < 32; ++t) B[t] = 0.0f;
        B[lane] = 1.0f;
#pragma unroll
        for (int t = 1; t < 32; ++t) {
            float s = 0.0f;
#pragma unroll
            for (int x = 0; x < t; ++x)
                s = fmaf(B[x], __half2float(Ab[t * SROW + x]), s);
            if (t > lane) B[t] = s;
        }
        float* Bo = Binv_s + warp * 32 * BINV_STRIDE + lane * BINV_STRIDE;
#pragma unroll
        for (int t = 0; t < 32; ++t) Bo[t] = B[t];
    }
    __syncthreads();

    for (int d = 0; d < d0; ++d)
        g_W[r * NVARS + d * 32 + lane] = __float2half(0.0f);

    const int j0 = d0 * 32;
    for (int d = d0; d < 8; ++d) {
        const int c0 = d * 32;
        float v;
        if (d == d0) {
            v = Binv_s[d0 * 32 * BINV_STRIDE + (r & 31) * BINV_STRIDE + lane];
        } else {
            const __half* Arow = A_s + (c0 + lane) * SROW;
            float s0 = 0.f, s1 = 0.f, s2 = 0.f, s3 = 0.f;
            for (int j = j0; j < c0; j += 8) {
                const uint4 u = *reinterpret_cast<const uint4*>(Arow + j);
                const __half2* h = reinterpret_cast<const __half2*>(&u);
                const float2 f0 = __half22float2(h[0]);
                const float2 f1 = __half22float2(h[1]);
                const float2 f2 = __half22float2(h[2]);
                const float2 f3 = __half22float2(h[3]);
                s0 = fmaf(Vsm[j + 0], f0.x, s0);
                s1 = fmaf(Vsm[j + 1], f0.y, s1);
                s2 = fmaf(Vsm[j + 2], f1.x, s2);
                s3 = fmaf(Vsm[j + 3], f1.y, s3);
                s0 = fmaf(Vsm[j + 4], f2.x, s0);
                s1 = fmaf(Vsm[j + 5], f2.y, s1);
                s2 = fmaf(Vsm[j + 6], f3.x, s2);
                s3 = fmaf(Vsm[j + 7], f3.y, s3);
            }
            const float S = (s0 + s1) + (s2 + s3);
            v = 0.0f;
            const float* Bi = Binv_s + d * 32 * BINV_STRIDE + lane;
#pragma unroll
            for (int u = 0; u < 32; ++u) {
                const float su = __shfl_sync(0xffffffffu, S, u);
                v = fmaf(su, Bi[u * BINV_STRIDE], v);
            }
        }
        Vsm[c0 + lane] = v;
        __syncwarp();
        g_W[r * NVARS + c0 + lane] = __float2half((c0 + lane > r) ? v : 0.0f);
    }
}

// ---------------------------------------------------------------------------
// Kernel 2: persistent GEMM with triangular k-skipping.
// R3 config: BM=32, 256 thr, W full resident, double-buffered Z + reg
// prefetch. Warp tile 16x64 on N chunk nc with k starting at nc*64:
//   nc = [0,1,2,3,3,2,1,0][wid], wm = wid>>2 -> every SMSP does 20 k-steps.
// ---------------------------------------------------------------------------
static constexpr int SMEM_W_HALVES = NVARS * SROW;  // 67584
static constexpr int SMEM_Z_HALVES = BM * SROW;     // 8448 per buf
static constexpr int SMEM_BYTES = (SMEM_W_HALVES + 2 * SMEM_Z_HALVES) * 2;  // 168960

__global__ __launch_bounds__(256, 1) void gemm_kernel(const float* __restrict__ Z,
                                                      float* __restrict__ out,
                                                      int batch, int ntiles) {
    extern __shared__ __align__(16) __half smem[];
    __half* Ws = smem;
    __half* Zbuf0 = smem + SMEM_W_HALVES;
    __half* Zbuf1 = Zbuf0 + SMEM_Z_HALVES;

    const int tid = threadIdx.x;
    const int lane = tid & 31;
    const int wid = tid >> 5;
    const int wm = wid >> 2;                       // M half (16 rows)
    const int nc = (wid < 4) ? wid : (7 - wid);    // N chunk (64 cols)
    const int kstart = nc * 4;                     // first k-step (k>=nc*64)

    // --- load W into smem once ---
    for (int idx = tid; idx < NVARS * 32; idx += 256) {
        const int row = idx >> 5;
        const int seg = idx & 31;
        *reinterpret_cast<uint4*>(Ws + row * SROW + seg * 8) =
            *reinterpret_cast<const uint4*>(g_W + row * NVARS + seg * 8);
    }

    // --- fragment addresses ---
    const uint32_t wbase = smem_to_u32(Ws);
    uint32_t baddr[4];
#pragma unroll
    for (int bj = 0; bj < 4; ++bj) {
        const int row = nc * 64 + bj * 16 + (lane & 7) + (((lane >> 4) & 1) * 8);
        const int cb = (lane & 8) ? 16 : 0;
        baddr[bj] = wbase + (uint32_t)row * (SROW * 2) + cb;
    }
    const int arow = wm * 16 + (lane & 15);
    const uint32_t acb = ((lane >> 4) & 1) * 16;

    // --- prefetch first tile (fp16-converted in regs) ---
    uint4 pf[4];
    int tile = blockIdx.x;
#pragma unroll
    for (int i = 0; i < 4; ++i) {
        const int idx = tid + i * 256;
        const int row = idx >> 5, seg = idx & 31;
        const int gr = tile * BM + row;
        if (tile < ntiles && gr < batch) {
            const float4* p =
                reinterpret_cast<const float4*>(Z + (size_t)gr * NVARS + seg * 8);
            pf[i] = cvt8_f32_to_h8(p[0], p[1]);
        } else {
            pf[i] = make_uint4(0, 0, 0, 0);
        }
    }

    int parity = 0;
    const int rrow = lane >> 2;
    const int rcol = (lane & 3) * 2;

    for (; tile < ntiles; tile += gridDim.x) {
        __half* Zs = parity ? Zbuf1 : Zbuf0;

        // store prefetched tile
#pragma unroll
        for (int i = 0; i < 4; ++i) {
            const int idx = tid + i * 256;
            const int row = idx >> 5, seg = idx & 31;
            *reinterpret_cast<uint4*>(Zs + row * SROW + seg * 8) = pf[i];
        }

        // prefetch next tile (latency hidden under MMA)
        const int nt = tile + gridDim.x;
        if (nt < ntiles) {
#pragma unroll
            for (int i = 0; i < 4; ++i) {
                const int idx = tid + i * 256;
                const int row = idx >> 5, seg = idx & 31;
                const int gr = nt * BM + row;
                if (gr < batch) {
                    const float4* p =
                        reinterpret_cast<const float4*>(Z + (size_t)gr * NVARS + seg * 8);
                    pf[i] = cvt8_f32_to_h8(p[0], p[1]);
                } else {
                    pf[i] = make_uint4(0, 0, 0, 0);
                }
            }
        }

        __syncthreads();  // staging visible; other buffer free

        const uint32_t zbase = smem_to_u32(Zs);
        const uint32_t aaddr = zbase + (uint32_t)arow * (SROW * 2) + acb;

        float acc[8][4];
#pragma unroll
        for (int nj = 0; nj < 8; ++nj)
#pragma unroll
            for (int e = 0; e < 4; ++e) acc[nj][e] = 0.0f;

        // k-steps [kstart, 16): triangular skip, balanced across SMSPs
#pragma unroll 4
        for (int k = kstart; k < 16; ++k) {
            uint32_t a[4], b[4][4];
            ldmx4(a, aaddr + k * 32);
#pragma unroll
            for (int bj = 0; bj < 4; ++bj) ldmx4(b[bj], baddr[bj] + k * 32);
#pragma unroll
            for (int nj = 0; nj < 8; ++nj) {
                const int bj = nj >> 1;
                const int hi = (nj & 1) * 2;
                mma16816(acc[nj], a, b[bj][hi + 0], b[bj][hi + 1]);
            }
        }

        // --- epilogue: out = Z(fp32, L2-hot) + acc ---
        const int r0 = tile * BM + wm * 16 + rrow;
        const int r1 = r0 + 8;
#pragma unroll
        for (int nj = 0; nj < 8; ++nj) {
            const int c = nc * 64 + nj * 8 + rcol;
            if (r0 < batch) {
                const float2 z0 =
                    *reinterpret_cast<const float2*>(Z + (size_t)r0 * NVARS + c);
                float2 o0;
                o0.x = z0.x + acc[nj][0];
                o0.y = z0.y + acc[nj][1];
                *reinterpret_cast<float2*>(out + (size_t)r0 * NVARS + c) = o0;
            }
            if (r1 < batch) {
                const float2 z1 =
                    *reinterpret_cast<const float2*>(Z + (size_t)r1 * NVARS + c);
                float2 o1;
                o1.x = z1.x + acc[nj][2];
                o1.y = z1.y + acc[nj][3];
                *reinterpret_cast<float2*>(out + (size_t)r1 * NVARS + c) = o1;
            }
        }

        parity ^= 1;
    }
}

// ---------------------------------------------------------------------------
extern "C" void kernel_launch(void* const* d_in, const int* in_sizes, int n_in,
                              void* d_out, int out_size) {
    const float* Z = (const float*)d_in[0];
    const float* A = (const float*)d_in[1];
    float* out = (float*)d_out;
    const int batch = in_sizes[0] / NVARS;
    const int ntiles = (batch + BM - 1) / BM;

    cudaFuncSetAttribute(gemm_kernel, cudaFuncAttributeMaxDynamicSharedMemorySize,
                         SMEM_BYTES);
    cudaFuncSetAttribute(invmain_kernel, cudaFuncAttributeMaxDynamicSharedMemorySize,
                         IM_SMEM);

    invmain_kernel<<<32, 256, IM_SMEM>>>(A);

    int grid = 152;
    if (ntiles < grid) grid = ntiles;
    gemm_kernel<<<grid, 256, SMEM_BYTES>>>(Z, out, batch, ntiles);
}

// round 14
// speedup vs baseline: 1.4556x; 1.1809x over previous
#include <cuda_runtime.h>
#include <cuda_fp16.h>
#include <cstdint>

#define NVARS 256
#define BM 32
#define SROW 264  // halves per padded smem row (528B): conflict-free ldmatrix/LDS.128

// W[n][k] = V[n][k] for k>=n else 0 (V = M^{-1}, unit diag INCLUDED: identity
// flows through the MMA; epilogue is store-only)
__device__ __half g_W[NVARS * NVARS];

__device__ __forceinline__ uint32_t smem_to_u32(const void* smem_ptr) {
    uint32_t addr;
    asm("{ .reg .u64 tmp; cvta.to.shared.u64 tmp, %1; cvt.u32.u64 %0, tmp; }"
        : "=r"(addr) : "l"(smem_ptr));
    return addr;
}

__device__ __forceinline__ void ldmx4(uint32_t* d, uint32_t addr) {
    asm volatile("ldmatrix.sync.aligned.m8n8.x4.shared.b16 {%0,%1,%2,%3}, [%4];"
                 : "=r"(d[0]), "=r"(d[1]), "=r"(d[2]), "=r"(d[3])
                 : "r"(addr));
}

__device__ __forceinline__ void mma16816(float* c, const uint32_t* a,
                                         uint32_t b0, uint32_t b1) {
    asm volatile(
        "mma.sync.aligned.m16n8k16.row.col.f32.f16.f16.f32 "
        "{%0,%1,%2,%3}, {%4,%5,%6,%7}, {%8,%9}, {%0,%1,%2,%3};"
        : "+f"(c[0]), "+f"(c[1]), "+f"(c[2]), "+f"(c[3])
        : "r"(a[0]), "r"(a[1]), "r"(a[2]), "r"(a[3]), "r"(b0), "r"(b1));
}

__device__ __forceinline__ uint4 cvt8_f32_to_h8(const float4 f0, const float4 f1) {
    __half2 h0 = __floats2half2_rn(f0.x, f0.y);
    __half2 h1 = __floats2half2_rn(f0.z, f0.w);
    __half2 h2 = __floats2half2_rn(f1.x, f1.y);
    __half2 h3 = __floats2half2_rn(f1.z, f1.w);
    uint4 u;
    u.x = *reinterpret_cast<uint32_t*>(&h0);
    u.y = *reinterpret_cast<uint32_t*>(&h1);
    u.z = *reinterpret_cast<uint32_t*>(&h2);
    u.w = *reinterpret_cast<uint32_t*>(&h3);
    return u;
}

// ---------------------------------------------------------------------------
// Kernel 1: triangular inverse (fused). 32 CTAs x 256 thr; warp per row r.
// ---------------------------------------------------------------------------
static constexpr int IM_A_HALVES = NVARS * SROW;  // 67584
static constexpr int BINV_STRIDE = 33;            // padded: conflict-free rows
static constexpr int IM_BINV_FLOATS = 8 * 32 * BINV_STRIDE;  // 8448
static constexpr int IM_SMEM =
    IM_A_HALVES * 2 + IM_BINV_FLOATS * 4 + 8 * NVARS * 4;  // 177152

__global__ __launch_bounds__(256) void invmain_kernel(const float* __restrict__ A) {
    extern __shared__ __align__(16) char sm_raw[];
    __half* A_s = reinterpret_cast<__half*>(sm_raw);
    float* Binv_s = reinterpret_cast<float*>(sm_raw + IM_A_HALVES * 2);
    float(*Vsm_all)[NVARS] = reinterpret_cast<float(*)[NVARS]>(
        sm_raw + IM_A_HALVES * 2 + IM_BINV_FLOATS * 4);

    const int tid = threadIdx.x;
    const int warp = tid >> 5;
    const int lane = tid & 31;
    const int r = blockIdx.x * 8 + warp;
    const int d0 = r >> 5;
    const int j0c = (blockIdx.x >> 2) * 32;  // first A row this CTA needs
    float* Vsm = Vsm_all[warp];

    for (int idx = tid; idx < (NVARS - j0c) * 64; idx += 256) {
        const int row = j0c + (idx >> 6);
        const int cs = (idx & 63) * 4;
        const float4 f = *reinterpret_cast<const float4*>(A + (size_t)row * NVARS + cs);
        __half2 h0 = __floats2half2_rn(f.x, f.y);
        __half2 h1 = __floats2half2_rn(f.z, f.w);
        uint2 u;
        u.x = *reinterpret_cast<uint32_t*>(&h0);
        u.y = *reinterpret_cast<uint32_t*>(&h1);
        *reinterpret_cast<uint2*>(A_s + row * SROW + cs) = u;
    }
    __syncthreads();

    if (warp >= d0) {
        const int c0 = warp * 32;
        const __half* Ab = A_s + (size_t)c0 * SROW + c0;
        float B[32];
#pragma unroll
        for (int t = 0; t < 32; ++t) B[t] = 0.0f;
        B[lane] = 1.0f;
#pragma unroll
        for (int t = 1; t < 32; ++t) {
            float s = 0.0f;
#pragma unroll
            for (int x = 0; x < t; ++x)
                s = fmaf(B[x], __half2float(Ab[t * SROW + x]), s);
            if (t > lane) B[t] = s;
        }
        float* Bo = Binv_s + warp * 32 * BINV_STRIDE + lane * BINV_STRIDE;
#pragma unroll
        for (int t = 0; t < 32; ++t) Bo[t] = B[t];
    }
    __syncthreads();

    for (int d = 0; d < d0; ++d)
        g_W[r * NVARS + d * 32 + lane] = __float2half(0.0f);

    const int j0 = d0 * 32;
    for (int d = d0; d < 8; ++d) {
        const int c0 = d * 32;
        float v;
        if (d == d0) {
            v = Binv_s[d0 * 32 * BINV_STRIDE + (r & 31) * BINV_STRIDE + lane];
        } else {
            const __half* Arow = A_s + (c0 + lane) * SROW;
            float s0 = 0.f, s1 = 0.f, s2 = 0.f, s3 = 0.f;
            for (int j = j0; j < c0; j += 8) {
                const uint4 u = *reinterpret_cast<const uint4*>(Arow + j);
                const __half2* h = reinterpret_cast<const __half2*>(&u);
                const float2 f0 = __half22float2(h[0]);
                const float2 f1 = __half22float2(h[1]);
                const float2 f2 = __half22float2(h[2]);
                const float2 f3 = __half22float2(h[3]);
                s0 = fmaf(Vsm[j + 0], f0.x, s0);
                s1 = fmaf(Vsm[j + 1], f0.y, s1);
                s2 = fmaf(Vsm[j + 2], f1.x, s2);
                s3 = fmaf(Vsm[j + 3], f1.y, s3);
                s0 = fmaf(Vsm[j + 4], f2.x, s0);
                s1 = fmaf(Vsm[j + 5], f2.y, s1);
                s2 = fmaf(Vsm[j + 6], f3.x, s2);
                s3 = fmaf(Vsm[j + 7], f3.y, s3);
            }
            const float S = (s0 + s1) + (s2 + s3);
            v = 0.0f;
            const float* Bi = Binv_s + d * 32 * BINV_STRIDE + lane;
#pragma unroll
            for (int u = 0; u < 32; ++u) {
                const float su = __shfl_sync(0xffffffffu, S, u);
                v = fmaf(su, Bi[u * BINV_STRIDE], v);
            }
        }
        Vsm[c0 + lane] = v;
        __syncwarp();
        // diag included: V[r][r] = 1.0 (exact in fp16) -> identity via MMA
        g_W[r * NVARS + c0 + lane] = __float2half((c0 + lane >= r) ? v : 0.0f);
    }
}

// ---------------------------------------------------------------------------
// Kernel 2: persistent GEMM, triangular skip with compile-time-unrolled
// mainloops, store-only epilogue.
// BM=32, 256 thr, W full resident, double-buffered Z + reg prefetch.
// Warp tile 16x64 on N chunk nc, k-steps [4*nc, 16):
//   nc = [0,1,2,3,3,2,1,0][wid], wm = wid>>2 -> every SMSP does 20 k-steps.
// ---------------------------------------------------------------------------
static constexpr int SMEM_W_HALVES = NVARS * SROW;  // 67584
static constexpr int SMEM_Z_HALVES = BM * SROW;     // 8448 per buf
static constexpr int SMEM_BYTES = (SMEM_W_HALVES + 2 * SMEM_Z_HALVES) * 2;  // 168960

template <int KSTART>
__device__ __forceinline__ void mainloop_t(uint32_t aaddr, const uint32_t* baddr,
                                           float (*acc)[4]) {
#pragma unroll
    for (int k = KSTART; k < 16; ++k) {
        uint32_t a[4], b[4][4];
        ldmx4(a, aaddr + k * 32);
#pragma unroll
        for (int bj = 0; bj < 4; ++bj) ldmx4(b[bj], baddr[bj] + k * 32);
#pragma unroll
        for (int nj = 0; nj < 8; ++nj) {
            const int bj = nj >> 1;
            const int hi = (nj & 1) * 2;
            mma16816(acc[nj], a, b[bj][hi + 0], b[bj][hi + 1]);
        }
    }
}

__global__ __launch_bounds__(256, 1) void gemm_kernel(const float* __restrict__ Z,
                                                      float* __restrict__ out,
                                                      int batch, int ntiles) {
    extern __shared__ __align__(16) __half smem[];
    __half* Ws = smem;
    __half* Zbuf0 = smem + SMEM_W_HALVES;
    __half* Zbuf1 = Zbuf0 + SMEM_Z_HALVES;

    const int tid = threadIdx.x;
    const int lane = tid & 31;
    const int wid = tid >> 5;
    const int wm = wid >> 2;                     // M half (16 rows)
    const int nc = (wid < 4) ? wid : (7 - wid);  // N chunk (64 cols)

    // --- load W into smem once ---
    for (int idx = tid; idx < NVARS * 32; idx += 256) {
        const int row = idx >> 5;
        const int seg = idx & 31;
        *reinterpret_cast<uint4*>(Ws + row * SROW + seg * 8) =
            *reinterpret_cast<const uint4*>(g_W + row * NVARS + seg * 8);
    }

    // --- fragment addresses ---
    const uint32_t wbase = smem_to_u32(Ws);
    uint32_t baddr[4];
#pragma unroll
    for (int bj = 0; bj < 4; ++bj) {
        const int row = nc * 64 + bj * 16 + (lane & 7) + (((lane >> 4) & 1) * 8);
        const int cb = (lane & 8) ? 16 : 0;
        baddr[bj] = wbase + (uint32_t)row * (SROW * 2) + cb;
    }
    const int arow = wm * 16 + (lane & 15);
    const uint32_t acb = ((lane >> 4) & 1) * 16;

    // --- prefetch first tile (fp16-converted in regs) ---
    uint4 pf[4];
    int tile = blockIdx.x;
#pragma unroll
    for (int i = 0; i < 4; ++i) {
        const int idx = tid + i * 256;
        const int row = idx >> 5, seg = idx & 31;
        const int gr = tile * BM + row;
        if (tile < ntiles && gr < batch) {
            const float4* p =
                reinterpret_cast<const float4*>(Z + (size_t)gr * NVARS + seg * 8);
            pf[i] = cvt8_f32_to_h8(p[0], p[1]);
        } else {
            pf[i] = make_uint4(0, 0, 0, 0);
        }
    }

    int parity = 0;
    const int rrow = lane >> 2;
    const int rcol = (lane & 3) * 2;

    for (; tile < ntiles; tile += gridDim.x) {
        __half* Zs = parity ? Zbuf1 : Zbuf0;

        // store prefetched tile
#pragma unroll
        for (int i = 0; i < 4; ++i) {
            const int idx = tid + i * 256;
            const int row = idx >> 5, seg = idx & 31;
            *reinterpret_cast<uint4*>(Zs + row * SROW + seg * 8) = pf[i];
        }

        // prefetch next tile (latency hidden under MMA)
        const int nt = tile + gridDim.x;
        if (nt < ntiles) {
#pragma unroll
            for (int i = 0; i < 4; ++i) {
                const int idx = tid + i * 256;
                const int row = idx >> 5, seg = idx & 31;
                const int gr = nt * BM + row;
                if (gr < batch) {
                    const float4* p =
                        reinterpret_cast<const float4*>(Z + (size_t)gr * NVARS + seg * 8);
                    pf[i] = cvt8_f32_to_h8(p[0], p[1]);
                } else {
                    pf[i] = make_uint4(0, 0, 0, 0);
                }
            }
        }

        __syncthreads();  // staging visible; other buffer free

        const uint32_t zbase = smem_to_u32(Zs);
        const uint32_t aaddr = zbase + (uint32_t)arow * (SROW * 2) + acb;

        float acc[8][4];
#pragma unroll
        for (int nj = 0; nj < 8; ++nj)
#pragma unroll
            for (int e = 0; e < 4; ++e) acc[nj][e] = 0.0f;

        // warp-uniform dispatch to fully-unrolled mainloops
        switch (nc) {
            case 0: mainloop_t<0>(aaddr, baddr, acc); break;
            case 1: mainloop_t<4>(aaddr, baddr, acc); break;
            case 2: mainloop_t<8>(aaddr, baddr, acc); break;
            default: mainloop_t<12>(aaddr, baddr, acc); break;
        }

        // --- epilogue: store-only (identity already in W) ---
        const int r0 = tile * BM + wm * 16 + rrow;
        const int r1 = r0 + 8;
#pragma unroll
        for (int nj = 0; nj < 8; ++nj) {
            const int c = nc * 64 + nj * 8 + rcol;
            if (r0 < batch) {
                float2 o0;
                o0.x = acc[nj][0];
                o0.y = acc[nj][1];
                *reinterpret_cast<float2*>(out + (size_t)r0 * NVARS + c) = o0;
            }
            if (r1 < batch) {
                float2 o1;
                o1.x = acc[nj][2];
                o1.y = acc[nj][3];
                *reinterpret_cast<float2*>(out + (size_t)r1 * NVARS + c) = o1;
            }
        }

        parity ^= 1;
    }
}

// ---------------------------------------------------------------------------
extern "C" void kernel_launch(void* const* d_in, const int* in_sizes, int n_in,
                              void* d_out, int out_size) {
    const float* Z = (const float*)d_in[0];
    const float* A = (const float*)d_in[1];
    float* out = (float*)d_out;
    const int batch = in_sizes[0] / NVARS;
    const int ntiles = (batch + BM - 1) / BM;

    cudaFuncSetAttribute(gemm_kernel, cudaFuncAttributeMaxDynamicSharedMemorySize,
                         SMEM_BYTES);
    cudaFuncSetAttribute(invmain_kernel, cudaFuncAttributeMaxDynamicSharedMemorySize,
                         IM_SMEM);

    invmain_kernel<<<32, 256, IM_SMEM>>>(A);

    int grid = 152;
    if (ntiles < grid) grid = ntiles;
    gemm_kernel<<<grid, 256, SMEM_BYTES>>>(Z, out, batch, ntiles);
}

// round 15
// speedup vs baseline: 1.5292x; 1.0506x over previous
#include <cuda_runtime.h>
#include <cuda_fp16.h>
#include <cstdint>

#define NVARS 256
#define BM 64
#define SROW 264  // halves per padded smem row (528B): conflict-free ldmatrix/LDS.128

// W[n][k] = V[n][k] for k>=n else 0 (V = M^{-1}, unit diag INCLUDED: identity
// flows through the MMA; epilogue is store-only)
__device__ __half g_W[NVARS * NVARS];

__device__ __forceinline__ uint32_t smem_to_u32(const void* smem_ptr) {
    uint32_t addr;
    asm("{ .reg .u64 tmp; cvta.to.shared.u64 tmp, %1; cvt.u32.u64 %0, tmp; }"
        : "=r"(addr) : "l"(smem_ptr));
    return addr;
}

__device__ __forceinline__ void ldmx4(uint32_t* d, uint32_t addr) {
    asm volatile("ldmatrix.sync.aligned.m8n8.x4.shared.b16 {%0,%1,%2,%3}, [%4];"
                 : "=r"(d[0]), "=r"(d[1]), "=r"(d[2]), "=r"(d[3])
                 : "r"(addr));
}

__device__ __forceinline__ void mma16816(float* c, const uint32_t* a,
                                         uint32_t b0, uint32_t b1) {
    asm volatile(
        "mma.sync.aligned.m16n8k16.row.col.f32.f16.f16.f32 "
        "{%0,%1,%2,%3}, {%4,%5,%6,%7}, {%8,%9}, {%0,%1,%2,%3};"
        : "+f"(c[0]), "+f"(c[1]), "+f"(c[2]), "+f"(c[3])
        : "r"(a[0]), "r"(a[1]), "r"(a[2]), "r"(a[3]), "r"(b0), "r"(b1));
}

__device__ __forceinline__ uint4 cvt8_f32_to_h8(const float4 f0, const float4 f1) {
    __half2 h0 = __floats2half2_rn(f0.x, f0.y);
    __half2 h1 = __floats2half2_rn(f0.z, f0.w);
    __half2 h2 = __floats2half2_rn(f1.x, f1.y);
    __half2 h3 = __floats2half2_rn(f1.z, f1.w);
    uint4 u;
    u.x = *reinterpret_cast<uint32_t*>(&h0);
    u.y = *reinterpret_cast<uint32_t*>(&h1);
    u.z = *reinterpret_cast<uint32_t*>(&h2);
    u.w = *reinterpret_cast<uint32_t*>(&h3);
    return u;
}

// ---------------------------------------------------------------------------
// Kernel 1: triangular inverse (fused). 32 CTAs x 256 thr; warp per row r.
// ---------------------------------------------------------------------------
static constexpr int IM_A_HALVES = NVARS * SROW;  // 67584
static constexpr int BINV_STRIDE = 33;            // padded: conflict-free rows
static constexpr int IM_BINV_FLOATS = 8 * 32 * BINV_STRIDE;  // 8448
static constexpr int IM_SMEM =
    IM_A_HALVES * 2 + IM_BINV_FLOATS * 4 + 8 * NVARS * 4;  // 177152

__global__ __launch_bounds__(256) void invmain_kernel(const float* __restrict__ A) {
    extern __shared__ __align__(16) char sm_raw[];
    __half* A_s = reinterpret_cast<__half*>(sm_raw);
    float* Binv_s = reinterpret_cast<float*>(sm_raw + IM_A_HALVES * 2);
    float(*Vsm_all)[NVARS] = reinterpret_cast<float(*)[NVARS]>(
        sm_raw + IM_A_HALVES * 2 + IM_BINV_FLOATS * 4);

    const int tid = threadIdx.x;
    const int warp = tid >> 5;
    const int lane = tid & 31;
    const int r = blockIdx.x * 8 + warp;
    const int d0 = r >> 5;
    const int j0c = (blockIdx.x >> 2) * 32;  // first A row this CTA needs
    float* Vsm = Vsm_all[warp];

    for (int idx = tid; idx < (NVARS - j0c) * 64; idx += 256) {
        const int row = j0c + (idx >> 6);
        const int cs = (idx & 63) * 4;
        const float4 f = *reinterpret_cast<const float4*>(A + (size_t)row * NVARS + cs);
        __half2 h0 = __floats2half2_rn(f.x, f.y);
        __half2 h1 = __floats2half2_rn(f.z, f.w);
        uint2 u;
        u.x = *reinterpret_cast<uint32_t*>(&h0);
        u.y = *reinterpret_cast<uint32_t*>(&h1);
        *reinterpret_cast<uint2*>(A_s + row * SROW + cs) = u;
    }
    __syncthreads();

    if (warp >= d0) {
        const int c0 = warp * 32;
        const __half* Ab = A_s + (size_t)c0 * SROW + c0;
        float B[32];
#pragma unroll
        for (int t = 0; t < 32; ++t) B[t] = 0.0f;
        B[lane] = 1.0f;
#pragma unroll
        for (int t = 1; t < 32; ++t) {
            float s = 0.0f;
#pragma unroll
            for (int x = 0; x < t; ++x)
                s = fmaf(B[x], __half2float(Ab[t * SROW + x]), s);
            if (t > lane) B[t] = s;
        }
        float* Bo = Binv_s + warp * 32 * BINV_STRIDE + lane * BINV_STRIDE;
#pragma unroll
        for (int t = 0; t < 32; ++t) Bo[t] = B[t];
    }
    __syncthreads();

    for (int d = 0; d < d0; ++d)
        g_W[r * NVARS + d * 32 + lane] = __float2half(0.0f);

    const int j0 = d0 * 32;
    for (int d = d0; d < 8; ++d) {
        const int c0 = d * 32;
        float v;
        if (d == d0) {
            v = Binv_s[d0 * 32 * BINV_STRIDE + (r & 31) * BINV_STRIDE + lane];
        } else {
            const __half* Arow = A_s + (c0 + lane) * SROW;
            float s0 = 0.f, s1 = 0.f, s2 = 0.f, s3 = 0.f;
            for (int j = j0; j < c0; j += 8) {
                const uint4 u = *reinterpret_cast<const uint4*>(Arow + j);
                const __half2* h = reinterpret_cast<const __half2*>(&u);
                const float2 f0 = __half22float2(h[0]);
                const float2 f1 = __half22float2(h[1]);
                const float2 f2 = __half22float2(h[2]);
                const float2 f3 = __half22float2(h[3]);
                s0 = fmaf(Vsm[j + 0], f0.x, s0);
                s1 = fmaf(Vsm[j + 1], f0.y, s1);
                s2 = fmaf(Vsm[j + 2], f1.x, s2);
                s3 = fmaf(Vsm[j + 3], f1.y, s3);
                s0 = fmaf(Vsm[j + 4], f2.x, s0);
                s1 = fmaf(Vsm[j + 5], f2.y, s1);
                s2 = fmaf(Vsm[j + 6], f3.x, s2);
                s3 = fmaf(Vsm[j + 7], f3.y, s3);
            }
            const float S = (s0 + s1) + (s2 + s3);
            v = 0.0f;
            const float* Bi = Binv_s + d * 32 * BINV_STRIDE + lane;
#pragma unroll
            for (int u = 0; u < 32; ++u) {
                const float su = __shfl_sync(0xffffffffu, S, u);
                v = fmaf(su, Bi[u * BINV_STRIDE], v);
            }
        }
        Vsm[c0 + lane] = v;
        __syncwarp();
        // diag included: V[r][r] = 1.0 (exact in fp16) -> identity via MMA
        g_W[r * NVARS + c0 + lane] = __float2half((c0 + lane >= r) ? v : 0.0f);
    }
}

// ---------------------------------------------------------------------------
// Kernel 2: persistent GEMM, BM=64, triangular skip (templated mainloops),
// store-only epilogue. 256 thr, 8 warps, warp tile 32x64:
//   wm = wid>>2 (M half of 64), nc = [0,1,2,3,3,2,1,0][wid] (N chunk, 64 cols)
//   k-steps [4*nc, 16) -> every SMSP does 20 k-steps, balanced.
// W full resident (132KB) + 2 Z bufs (66KB) = 198KB, 1 CTA/SM, regs free to 255.
// ---------------------------------------------------------------------------
static constexpr int SMEM_W_HALVES = NVARS * SROW;  // 67584
static constexpr int SMEM_Z_HALVES = BM * SROW;     // 16896 per buf
static constexpr int SMEM_BYTES = (SMEM_W_HALVES + 2 * SMEM_Z_HALVES) * 2;  // 202752

template <int KSTART>
__device__ __forceinline__ void mainloop_t(const uint32_t* aaddr, const uint32_t* baddr,
                                           float (*acc)[8][4]) {
#pragma unroll
    for (int k = KSTART; k < 16; ++k) {
        uint32_t a[2][4], b[4][4];
        ldmx4(a[0], aaddr[0] + k * 32);
        ldmx4(a[1], aaddr[1] + k * 32);
#pragma unroll
        for (int bj = 0; bj < 4; ++bj) ldmx4(b[bj], baddr[bj] + k * 32);
#pragma unroll
        for (int mi = 0; mi < 2; ++mi)
#pragma unroll
            for (int nj = 0; nj < 8; ++nj) {
                const int bj = nj >> 1;
                const int hi = (nj & 1) * 2;
                mma16816(acc[mi][nj], a[mi], b[bj][hi + 0], b[bj][hi + 1]);
            }
    }
}

__global__ __launch_bounds__(256, 1) void gemm_kernel(const float* __restrict__ Z,
                                                      float* __restrict__ out,
                                                      int batch, int ntiles) {
    extern __shared__ __align__(16) __half smem[];
    __half* Ws = smem;
    __half* Zbuf0 = smem + SMEM_W_HALVES;
    __half* Zbuf1 = Zbuf0 + SMEM_Z_HALVES;

    const int tid = threadIdx.x;
    const int lane = tid & 31;
    const int wid = tid >> 5;
    const int wm = wid >> 2;                     // M half (32 rows of 64)
    const int nc = (wid < 4) ? wid : (7 - wid);  // N chunk (64 cols)

    // --- load W into smem once ---
    for (int idx = tid; idx < NVARS * 32; idx += 256) {
        const int row = idx >> 5;
        const int seg = idx & 31;
        *reinterpret_cast<uint4*>(Ws + row * SROW + seg * 8) =
            *reinterpret_cast<const uint4*>(g_W + row * NVARS + seg * 8);
    }

    // --- fragment addresses ---
    const uint32_t wbase = smem_to_u32(Ws);
    uint32_t baddr[4];
#pragma unroll
    for (int bj = 0; bj < 4; ++bj) {
        const int row = nc * 64 + bj * 16 + (lane & 7) + (((lane >> 4) & 1) * 8);
        const int cb = (lane & 8) ? 16 : 0;
        baddr[bj] = wbase + (uint32_t)row * (SROW * 2) + cb;
    }
    const int arow = wm * 32 + (lane & 15);
    const uint32_t acb = ((lane >> 4) & 1) * 16;

    // --- prefetch first tile (fp16-converted in regs, streaming loads) ---
    uint4 pf[8];
    int tile = blockIdx.x;
#pragma unroll
    for (int i = 0; i < 8; ++i) {
        const int idx = tid + i * 256;
        const int row = idx >> 5, seg = idx & 31;
        const int gr = tile * BM + row;
        if (tile < ntiles && gr < batch) {
            const float4* p =
                reinterpret_cast<const float4*>(Z + (size_t)gr * NVARS + seg * 8);
            pf[i] = cvt8_f32_to_h8(__ldcs(p), __ldcs(p + 1));
        } else {
            pf[i] = make_uint4(0, 0, 0, 0);
        }
    }

    int parity = 0;
    const int rrow = lane >> 2;
    const int rcol = (lane & 3) * 2;

    for (; tile < ntiles; tile += gridDim.x) {
        __half* Zs = parity ? Zbuf1 : Zbuf0;

        // store prefetched tile
#pragma unroll
        for (int i = 0; i < 8; ++i) {
            const int idx = tid + i * 256;
            const int row = idx >> 5, seg = idx & 31;
            *reinterpret_cast<uint4*>(Zs + row * SROW + seg * 8) = pf[i];
        }

        // prefetch next tile (latency hidden under MMA)
        const int nt = tile + gridDim.x;
        if (nt < ntiles) {
#pragma unroll
            for (int i = 0; i < 8; ++i) {
                const int idx = tid + i * 256;
                const int row = idx >> 5, seg = idx & 31;
                const int gr = nt * BM + row;
                if (gr < batch) {
                    const float4* p =
                        reinterpret_cast<const float4*>(Z + (size_t)gr * NVARS + seg * 8);
                    pf[i] = cvt8_f32_to_h8(__ldcs(p), __ldcs(p + 1));
                } else {
                    pf[i] = make_uint4(0, 0, 0, 0);
                }
            }
        }

        __syncthreads();  // staging visible; other buffer free

        const uint32_t zbase = smem_to_u32(Zs);
        uint32_t aaddr[2];
#pragma unroll
        for (int mi = 0; mi < 2; ++mi)
            aaddr[mi] = zbase + (uint32_t)(arow + mi * 16) * (SROW * 2) + acb;

        float acc[2][8][4];
#pragma unroll
        for (int mi = 0; mi < 2; ++mi)
#pragma unroll
            for (int nj = 0; nj < 8; ++nj)
#pragma unroll
                for (int e = 0; e < 4; ++e) acc[mi][nj][e] = 0.0f;

        // warp-uniform dispatch to fully-unrolled mainloops
        switch (nc) {
            case 0: mainloop_t<0>(aaddr, baddr, acc); break;
            case 1: mainloop_t<4>(aaddr, baddr, acc); break;
            case 2: mainloop_t<8>(aaddr, baddr, acc); break;
            default: mainloop_t<12>(aaddr, baddr, acc); break;
        }

        // --- epilogue: store-only, streaming (identity already in W) ---
#pragma unroll
        for (int mi = 0; mi < 2; ++mi) {
            const int r0 = tile * BM + wm * 32 + mi * 16 + rrow;
            const int r1 = r0 + 8;
#pragma unroll
            for (int nj = 0; nj < 8; ++nj) {
                const int c = nc * 64 + nj * 8 + rcol;
                if (r0 < batch) {
                    float2 o0;
                    o0.x = acc[mi][nj][0];
                    o0.y = acc[mi][nj][1];
                    __stcs(reinterpret_cast<float2*>(out + (size_t)r0 * NVARS + c), o0);
                }
                if (r1 < batch) {
                    float2 o1;
                    o1.x = acc[mi][nj][2];
                    o1.y = acc[mi][nj][3];
                    __stcs(reinterpret_cast<float2*>(out + (size_t)r1 * NVARS + c), o1);
                }
            }
        }

        parity ^= 1;
    }
}

// ---------------------------------------------------------------------------
extern "C" void kernel_launch(void* const* d_in, const int* in_sizes, int n_in,
                              void* d_out, int out_size) {
    const float* Z = (const float*)d_in[0];
    const float* A = (const float*)d_in[1];
    float* out = (float*)d_out;
    const int batch = in_sizes[0] / NVARS;
    const int ntiles = (batch + BM - 1) / BM;

    cudaFuncSetAttribute(gemm_kernel, cudaFuncAttributeMaxDynamicSharedMemorySize,
                         SMEM_BYTES);
    cudaFuncSetAttribute(invmain_kernel, cudaFuncAttributeMaxDynamicSharedMemorySize,
                         IM_SMEM);

    invmain_kernel<<<32, 256, IM_SMEM>>>(A);

    int grid = 152;
    if (ntiles < grid) grid = ntiles;
    gemm_kernel<<<grid, 256, SMEM_BYTES>>>(Z, out, batch, ntiles);
}